// round 13
// baseline (speedup 1.0000x reference)
#include <cuda_runtime.h>
#include <stdint.h>
#include <math.h>

typedef unsigned long long ull;

#define TSZ   524288u
#define TMASK 524287u
#define PI2   2654435761u
#define PI3   805459861u

// ---- dynamic shared memory float offsets ----
#define XS    68                 // X buffer row stride (68*4B=272B: 16B aligned, conflict-free A-loads)
#define OX    0                  // X: 32 x 68 = 2176
#define OW1   2176               // W1 [32][65] = 2080
#define OW2   4256               // W2 [64][17] = 1088
#define OW3   5344               // W3 [48][65] = 3120 (rows 43..47 zero)
#define OW4   8464               // W4 [64][65] = 4160
#define OW5   12624              // W5T [3][64] = 192
#define OB1   12816              // [64]
#define OB2   12880              // [16]
#define OB3   12896              // [64]
#define OB4   12960              // [64]
#define OB5   13024              // [3]+pad
#define SW_TOTAL 13028
#define SMEM_BYTES (SW_TOTAL * 4)

union F2 { float2 f; ull u; };

__device__ __forceinline__ uint32_t to_tf32(float f) {
    uint32_t r; asm("cvt.rna.tf32.f32 %0, %1;" : "=r"(r) : "f"(f)); return r;
}
__device__ __forceinline__ void mma8(float (&d)[4], const uint32_t (&a)[4], uint32_t b0, uint32_t b1) {
    asm volatile("mma.sync.aligned.m16n8k8.row.col.f32.tf32.tf32.f32 "
        "{%0,%1,%2,%3},{%4,%5,%6,%7},{%8,%9},{%0,%1,%2,%3};"
        : "+f"(d[0]), "+f"(d[1]), "+f"(d[2]), "+f"(d[3])
        : "r"(a[0]), "r"(a[1]), "r"(a[2]), "r"(a[3]), "r"(b0), "r"(b1));
}
// 3xTF32: hi*hi + lo*hi + hi*lo (error ~2^-22)
__device__ __forceinline__ void mma3(float (&d)[4], const uint32_t (&ah)[4], const uint32_t (&al)[4],
                                     uint32_t bh0, uint32_t bh1, uint32_t bl0, uint32_t bl1) {
    mma8(d, ah, bh0, bh1);
    mma8(d, al, bh0, bh1);
    mma8(d, ah, bl0, bl1);
}
__device__ __forceinline__ void loadA(const float* X, int mt, int kt, int gid4, int tig,
                                      uint32_t (&ah)[4], uint32_t (&al)[4]) {
    #pragma unroll
    for (int e = 0; e < 4; ++e) {
        int r = mt * 16 + gid4 + (e & 1) * 8;
        int c = kt * 8 + tig + (e >> 1) * 4;
        float v = X[r * XS + c];
        uint32_t h = to_tf32(v);
        ah[e] = h;
        al[e] = to_tf32(v - __uint_as_float(h));
    }
}
__device__ __forceinline__ void loadB(const float* W, int stride, int kt, int nt, int gid4, int tig,
                                      uint32_t &bh0, uint32_t &bh1, uint32_t &bl0, uint32_t &bl1) {
    float w0 = W[(kt * 8 + tig)     * stride + nt * 8 + gid4];
    float w1 = W[(kt * 8 + tig + 4) * stride + nt * 8 + gid4];
    bh0 = to_tf32(w0); bl0 = to_tf32(w0 - __uint_as_float(bh0));
    bh1 = to_tf32(w1); bl1 = to_tf32(w1 - __uint_as_float(bh1));
}

__global__ __launch_bounds__(128, 4) void ngp_kernel(
    const float* __restrict__ x, const float* __restrict__ dirs,
    const float* __restrict__ tables,
    const float* __restrict__ w1, const float* __restrict__ b1,
    const float* __restrict__ w2, const float* __restrict__ b2,
    const float* __restrict__ w3, const float* __restrict__ b3,
    const float* __restrict__ w4, const float* __restrict__ b4,
    const float* __restrict__ w5, const float* __restrict__ b5,
    float* __restrict__ out, int n)
{
    extern __shared__ float sw[];
    const int tid  = threadIdx.x;
    const int wid  = tid >> 5;
    const int lane = tid & 31;
    const int gid4 = lane >> 2;
    const int tig  = lane & 3;
    float* X = sw + OX;

    // ---- weight staging (padded strides for conflict-free B-fragment loads) ----
    for (int t = tid; t < 2048; t += 128) sw[OW1 + (t >> 6) * 65 + (t & 63)] = w1[t];
    for (int t = tid; t < 1024; t += 128) sw[OW2 + (t >> 4) * 17 + (t & 15)] = w2[t];
    for (int t = tid; t < 3120; t += 128) sw[OW3 + t] = 0.0f;
    for (int t = tid; t < 4096; t += 128) sw[OW4 + (t >> 6) * 65 + (t & 63)] = w4[t];
    for (int t = tid; t < 192;  t += 128) sw[OW5 + (t % 3) * 64 + (t / 3)] = w5[t];
    for (int t = tid; t < 64;   t += 128) { sw[OB1 + t] = b1[t]; sw[OB3 + t] = b3[t]; sw[OB4 + t] = b4[t]; }
    if (tid < 16) sw[OB2 + tid] = b2[tid];
    if (tid < 3)  sw[OB5 + tid] = b5[tid];
    __syncthreads();   // W3 zeros complete before fill
    for (int t = tid; t < 2752; t += 128) sw[OW3 + (t >> 6) * 65 + (t & 63)] = w3[t];

    // ---- per-thread point: encode (no early return — block-wide syncs below) ----
    const int gi = blockIdx.x * 128 + tid;
    const int li = (gi < n) ? gi : 0;

    float px = x[li * 3 + 0] * (1.0f / 3.0f);
    float py = x[li * 3 + 1] * (1.0f / 3.0f);
    float pz = x[li * 3 + 2] * (1.0f / 3.0f);
    bool inside = (fabsf(px) < 0.5f) && (fabsf(py) < 0.5f) && (fabsf(pz) < 0.5f);
    const float HI = 1.0f - 1e-7f;
    float ux = fminf(fmaxf(px + 0.5f, 0.0f), HI);
    float uy = fminf(fmaxf(py + 0.5f, 0.0f), HI);
    float uz = fminf(fmaxf(pz + 0.5f, 0.0f), HI);
    float dx = dirs[li * 3 + 0];
    float dy = dirs[li * 3 + 1];
    float dz = dirs[li * 3 + 2];

    const int NL[16] = {16, 22, 30, 42, 58, 80, 110, 152, 210, 290, 400, 552, 762, 1052, 1452, 2004};
    const float2* __restrict__ tab2 = reinterpret_cast<const float2*>(tables);

    F2 feat[16];
    #pragma unroll
    for (int L = 0; L < 16; ++L) {
        float sx = ux * (float)NL[L], sy = uy * (float)NL[L], sz = uz * (float)NL[L];
        float fx = floorf(sx), fy = floorf(sy), fz = floorf(sz);
        float tx = sx - fx, ty = sy - fy, tz = sz - fz;
        uint32_t xi0 = (uint32_t)fx, yi0 = (uint32_t)fy, zi0 = (uint32_t)fz;
        uint32_t xi1 = xi0 + 1u;
        uint32_t hy0 = yi0 * PI2, hy1 = hy0 + PI2;
        uint32_t hz0 = zi0 * PI3, hz1 = hz0 + PI3;
        const float2* tb = tab2 + (size_t)L * TSZ;
        float2 g0 = __ldg(tb + ((xi0 ^ hy0 ^ hz0) & TMASK));
        float2 g1 = __ldg(tb + ((xi1 ^ hy0 ^ hz0) & TMASK));
        float2 g2 = __ldg(tb + ((xi0 ^ hy1 ^ hz0) & TMASK));
        float2 g3 = __ldg(tb + ((xi1 ^ hy1 ^ hz0) & TMASK));
        float2 g4 = __ldg(tb + ((xi0 ^ hy0 ^ hz1) & TMASK));
        float2 g5 = __ldg(tb + ((xi1 ^ hy0 ^ hz1) & TMASK));
        float2 g6 = __ldg(tb + ((xi0 ^ hy1 ^ hz1) & TMASK));
        float2 g7 = __ldg(tb + ((xi1 ^ hy1 ^ hz1) & TMASK));
        float wx0 = 1.0f - tx, wy0 = 1.0f - ty, wz0 = 1.0f - tz;
        float w00 = wy0 * wz0, w10 = ty * wz0, w01 = wy0 * tz, w11 = ty * tz;
        float f0 = 0.0f, f1 = 0.0f, wgt;
        wgt = wx0 * w00; f0 = fmaf(wgt, g0.x, f0); f1 = fmaf(wgt, g0.y, f1);
        wgt = tx  * w00; f0 = fmaf(wgt, g1.x, f0); f1 = fmaf(wgt, g1.y, f1);
        wgt = wx0 * w10; f0 = fmaf(wgt, g2.x, f0); f1 = fmaf(wgt, g2.y, f1);
        wgt = tx  * w10; f0 = fmaf(wgt, g3.x, f0); f1 = fmaf(wgt, g3.y, f1);
        wgt = wx0 * w01; f0 = fmaf(wgt, g4.x, f0); f1 = fmaf(wgt, g4.y, f1);
        wgt = tx  * w01; f0 = fmaf(wgt, g5.x, f0); f1 = fmaf(wgt, g5.y, f1);
        wgt = wx0 * w11; f0 = fmaf(wgt, g6.x, f0); f1 = fmaf(wgt, g6.y, f1);
        wgt = tx  * w11; f0 = fmaf(wgt, g7.x, f0); f1 = fmaf(wgt, g7.y, f1);
        feat[L].f.x = f0; feat[L].f.y = f1;
    }

    float vr = 0.0f, vg = 0.0f, vb = 0.0f, sigma_my = 0.0f;

    // ---- 4 batches of 32 points (batch b = warp b's points); 4 warps cooperate ----
    for (int b = 0; b < 4; ++b) {
        __syncthreads();
        if (wid == b) {
            #pragma unroll
            for (int j = 0; j < 16; ++j)
                *reinterpret_cast<ull*>(&X[lane * XS + 2 * j]) = feat[j].u;
        }
        __syncthreads();

        // ---- L1: [32pts x 32] @ W1[32x64] -> relu ; warp w covers nt {2w, 2w+1} ----
        float d1[2][2][4];
        {
            const int ntb = wid * 2;
            #pragma unroll
            for (int ni = 0; ni < 2; ++ni) {
                float bv0 = sw[OB1 + (ntb + ni) * 8 + 2 * tig];
                float bv1 = sw[OB1 + (ntb + ni) * 8 + 2 * tig + 1];
                #pragma unroll
                for (int mt = 0; mt < 2; ++mt) {
                    d1[mt][ni][0] = bv0; d1[mt][ni][1] = bv1;
                    d1[mt][ni][2] = bv0; d1[mt][ni][3] = bv1;
                }
            }
            #pragma unroll
            for (int kt = 0; kt < 4; ++kt) {
                uint32_t ah[2][4], al[2][4];
                loadA(X, 0, kt, gid4, tig, ah[0], al[0]);
                loadA(X, 1, kt, gid4, tig, ah[1], al[1]);
                #pragma unroll
                for (int ni = 0; ni < 2; ++ni) {
                    uint32_t bh0, bh1, bl0, bl1;
                    loadB(sw + OW1, 65, kt, ntb + ni, gid4, tig, bh0, bh1, bl0, bl1);
                    mma3(d1[0][ni], ah[0], al[0], bh0, bh1, bl0, bl1);
                    mma3(d1[1][ni], ah[1], al[1], bh0, bh1, bl0, bl1);
                }
            }
        }
        __syncthreads();   // all reads of X0 done
        #pragma unroll
        for (int ni = 0; ni < 2; ++ni) {
            int c0 = (wid * 2 + ni) * 8 + 2 * tig;
            #pragma unroll
            for (int mt = 0; mt < 2; ++mt) {
                int r0 = mt * 16 + gid4;
                X[r0 * XS + c0]       = fmaxf(d1[mt][ni][0], 0.0f);
                X[r0 * XS + c0 + 1]   = fmaxf(d1[mt][ni][1], 0.0f);
                X[(r0+8) * XS + c0]   = fmaxf(d1[mt][ni][2], 0.0f);
                X[(r0+8) * XS + c0 + 1] = fmaxf(d1[mt][ni][3], 0.0f);
            }
        }
        __syncthreads();

        // ---- L2: [32 x 64] @ W2[64x16] (no relu); warp w -> (mt=w>>1, nt=w&1) ----
        float d2[4];
        {
            const int mt = wid >> 1, nt = wid & 1;
            d2[0] = d2[2] = sw[OB2 + nt * 8 + 2 * tig];
            d2[1] = d2[3] = sw[OB2 + nt * 8 + 2 * tig + 1];
            #pragma unroll
            for (int kt = 0; kt < 8; ++kt) {
                uint32_t ah[4], al[4], bh0, bh1, bl0, bl1;
                loadA(X, mt, kt, gid4, tig, ah, al);
                loadB(sw + OW2, 17, kt, nt, gid4, tig, bh0, bh1, bl0, bl1);
                mma3(d2, ah, al, bh0, bh1, bl0, bl1);
            }
        }
        __syncthreads();   // all reads of X1 done
        {   // store H2 raw into cols 27..42; warp b writes dir-enc cols 0..26 + zeros 43..47
            const int mt = wid >> 1, nt = wid & 1;
            int c0 = 27 + nt * 8 + 2 * tig;
            int r0 = mt * 16 + gid4;
            X[r0 * XS + c0]       = d2[0];
            X[r0 * XS + c0 + 1]   = d2[1];
            X[(r0+8) * XS + c0]   = d2[2];
            X[(r0+8) * XS + c0 + 1] = d2[3];
        }
        if (wid == b) {
            float* row = X + lane * XS;
            row[0] = dx; row[1] = dy; row[2] = dz;
            #pragma unroll
            for (int c = 0; c < 3; ++c) {
                float dc = (c == 0) ? dx : ((c == 1) ? dy : dz);
                #pragma unroll
                for (int fq = 0; fq < 4; ++fq) {
                    float ang = dc * (float)(1 << fq);
                    row[3 + c * 4 + fq]  = __sinf(ang);
                    row[15 + c * 4 + fq] = __cosf(ang);
                }
            }
            #pragma unroll
            for (int c = 43; c < 48; ++c) row[c] = 0.0f;
        }
        __syncthreads();
        if (wid == b) sigma_my = X[lane * XS + 27];

        // ---- L3: [32 x 48] @ W3[48x64] -> relu ----
        float d3[2][2][4];
        {
            const int ntb = wid * 2;
            #pragma unroll
            for (int ni = 0; ni < 2; ++ni) {
                float bv0 = sw[OB3 + (ntb + ni) * 8 + 2 * tig];
                float bv1 = sw[OB3 + (ntb + ni) * 8 + 2 * tig + 1];
                #pragma unroll
                for (int mt = 0; mt < 2; ++mt) {
                    d3[mt][ni][0] = bv0; d3[mt][ni][1] = bv1;
                    d3[mt][ni][2] = bv0; d3[mt][ni][3] = bv1;
                }
            }
            #pragma unroll
            for (int kt = 0; kt < 6; ++kt) {
                uint32_t ah[2][4], al[2][4];
                loadA(X, 0, kt, gid4, tig, ah[0], al[0]);
                loadA(X, 1, kt, gid4, tig, ah[1], al[1]);
                #pragma unroll
                for (int ni = 0; ni < 2; ++ni) {
                    uint32_t bh0, bh1, bl0, bl1;
                    loadB(sw + OW3, 65, kt, ntb + ni, gid4, tig, bh0, bh1, bl0, bl1);
                    mma3(d3[0][ni], ah[0], al[0], bh0, bh1, bl0, bl1);
                    mma3(d3[1][ni], ah[1], al[1], bh0, bh1, bl0, bl1);
                }
            }
        }
        __syncthreads();
        #pragma unroll
        for (int ni = 0; ni < 2; ++ni) {
            int c0 = (wid * 2 + ni) * 8 + 2 * tig;
            #pragma unroll
            for (int mt = 0; mt < 2; ++mt) {
                int r0 = mt * 16 + gid4;
                X[r0 * XS + c0]       = fmaxf(d3[mt][ni][0], 0.0f);
                X[r0 * XS + c0 + 1]   = fmaxf(d3[mt][ni][1], 0.0f);
                X[(r0+8) * XS + c0]   = fmaxf(d3[mt][ni][2], 0.0f);
                X[(r0+8) * XS + c0 + 1] = fmaxf(d3[mt][ni][3], 0.0f);
            }
        }
        __syncthreads();

        // ---- L4: [32 x 64] @ W4[64x64] -> relu ----
        float d4[2][2][4];
        {
            const int ntb = wid * 2;
            #pragma unroll
            for (int ni = 0; ni < 2; ++ni) {
                float bv0 = sw[OB4 + (ntb + ni) * 8 + 2 * tig];
                float bv1 = sw[OB4 + (ntb + ni) * 8 + 2 * tig + 1];
                #pragma unroll
                for (int mt = 0; mt < 2; ++mt) {
                    d4[mt][ni][0] = bv0; d4[mt][ni][1] = bv1;
                    d4[mt][ni][2] = bv0; d4[mt][ni][3] = bv1;
                }
            }
            #pragma unroll
            for (int kt = 0; kt < 8; ++kt) {
                uint32_t ah[2][4], al[2][4];
                loadA(X, 0, kt, gid4, tig, ah[0], al[0]);
                loadA(X, 1, kt, gid4, tig, ah[1], al[1]);
                #pragma unroll
                for (int ni = 0; ni < 2; ++ni) {
                    uint32_t bh0, bh1, bl0, bl1;
                    loadB(sw + OW4, 65, kt, ntb + ni, gid4, tig, bh0, bh1, bl0, bl1);
                    mma3(d4[0][ni], ah[0], al[0], bh0, bh1, bl0, bl1);
                    mma3(d4[1][ni], ah[1], al[1], bh0, bh1, bl0, bl1);
                }
            }
        }
        __syncthreads();
        #pragma unroll
        for (int ni = 0; ni < 2; ++ni) {
            int c0 = (wid * 2 + ni) * 8 + 2 * tig;
            #pragma unroll
            for (int mt = 0; mt < 2; ++mt) {
                int r0 = mt * 16 + gid4;
                X[r0 * XS + c0]       = fmaxf(d4[mt][ni][0], 0.0f);
                X[r0 * XS + c0 + 1]   = fmaxf(d4[mt][ni][1], 0.0f);
                X[(r0+8) * XS + c0]   = fmaxf(d4[mt][ni][2], 0.0f);
                X[(r0+8) * XS + c0 + 1] = fmaxf(d4[mt][ni][3], 0.0f);
            }
        }
        __syncthreads();

        // ---- L5: 64 -> 3 (scalar, warp b only; X safe until next batch fill) ----
        if (wid == b) {
            const float* row = X + lane * XS;
            float ar = sw[OB5 + 0], ag = sw[OB5 + 1], ab = sw[OB5 + 2];
            #pragma unroll
            for (int i = 0; i < 64; ++i) {
                float a = row[i];
                ar = fmaf(a, sw[OW5 + i],       ar);
                ag = fmaf(a, sw[OW5 + 64 + i],  ag);
                ab = fmaf(a, sw[OW5 + 128 + i], ab);
            }
            vr = ar; vg = ag; vb = ab;
        }
    }

    // ---- outputs: [N,3] color then [N] log_sigma ----
    if (gi < n) {
        float cr = inside ? 1.0f / (1.0f + __expf(-vr)) : 0.0f;
        float cg = inside ? 1.0f / (1.0f + __expf(-vg)) : 0.0f;
        float cb = inside ? 1.0f / (1.0f + __expf(-vb)) : 0.0f;
        out[gi * 3 + 0] = cr;
        out[gi * 3 + 1] = cg;
        out[gi * 3 + 2] = cb;
        out[(size_t)3 * n + gi] = inside ? sigma_my : -100000.0f;
    }
}

extern "C" void kernel_launch(void* const* d_in, const int* in_sizes, int n_in,
                              void* d_out, int out_size) {
    const float* x      = (const float*)d_in[0];
    const float* d      = (const float*)d_in[1];
    const float* tables = (const float*)d_in[2];
    const float* w1 = (const float*)d_in[3];
    const float* b1 = (const float*)d_in[4];
    const float* w2 = (const float*)d_in[5];
    const float* b2 = (const float*)d_in[6];
    const float* w3 = (const float*)d_in[7];
    const float* b3 = (const float*)d_in[8];
    const float* w4 = (const float*)d_in[9];
    const float* b4 = (const float*)d_in[10];
    const float* w5 = (const float*)d_in[11];
    const float* b5 = (const float*)d_in[12];
    float* out = (float*)d_out;

    cudaFuncSetAttribute(ngp_kernel, cudaFuncAttributeMaxDynamicSharedMemorySize, SMEM_BYTES);

    int n = in_sizes[0] / 3;
    int blocks = (n + 127) / 128;
    ngp_kernel<<<blocks, 128, SMEM_BYTES>>>(x, d, tables, w1, b1, w2, b2, w3, b3, w4, b4, w5, b5, out, n);
}

// round 14
// speedup vs baseline: 1.1249x; 1.1249x over previous
#include <cuda_runtime.h>
#include <stdint.h>
#include <math.h>

typedef unsigned long long ull;

#define TSZ   524288u
#define TMASK 524287u
#define PI2   2654435761u
#define PI3   805459861u

#define XS 68      // X row stride (floats): A-load bank-conflict-free (4*gid4+tig unique)
#define WS 72      // weight row stride: B-load conflict-free (72 mod 32 == 8 -> 8*tig+gid4 unique)

// ---- dynamic shared memory float offsets ----
#define OX   0                       // 16 warps x 32 x 68 = 34816
#define OW1  34816                   // [32][72] = 2304
#define OW2  37120                   // [64][24] = 1536 (24 mod 32 -> conflict-free)
#define OW3  38656                   // [48][72] = 3456 (rows 43..47 zero)
#define OW4  42112                   // [64][72] = 4608
#define OW5  46720                   // [64][8]  = 512  (cols 0..2 real, 3..7 zero)
#define OB1  47232                   // 64
#define OB2  47296                   // 16
#define OB3  47312                   // 64
#define OB4  47376                   // 64
#define OB5  47440                   // 4
#define SW_TOTAL 47444
#define SMEM_BYTES (SW_TOTAL * 4)    // 189776 B

union F2 { float2 f; ull u; };

__device__ __forceinline__ uint32_t to_tf32(float f) {
    uint32_t r; asm("cvt.rna.tf32.f32 %0, %1;" : "=r"(r) : "f"(f)); return r;
}
__device__ __forceinline__ void mma8(float (&d)[4], const uint32_t (&a)[4], uint32_t b0, uint32_t b1) {
    asm volatile("mma.sync.aligned.m16n8k8.row.col.f32.tf32.tf32.f32 "
        "{%0,%1,%2,%3},{%4,%5,%6,%7},{%8,%9},{%0,%1,%2,%3};"
        : "+f"(d[0]), "+f"(d[1]), "+f"(d[2]), "+f"(d[3])
        : "r"(a[0]), "r"(a[1]), "r"(a[2]), "r"(a[3]), "r"(b0), "r"(b1));
}
// 3xTF32: hi*hi + lo*hi + hi*lo (error ~2^-22)
__device__ __forceinline__ void mma3(float (&d)[4], const uint32_t (&ah)[4], const uint32_t (&al)[4],
                                     uint32_t bh0, uint32_t bh1, uint32_t bl0, uint32_t bl1) {
    mma8(d, ah, bh0, bh1);
    mma8(d, al, bh0, bh1);
    mma8(d, ah, bl0, bl1);
}
__device__ __forceinline__ void loadA(const float* Xp, int mt, int kt, int gid4, int tig,
                                      uint32_t (&ah)[4], uint32_t (&al)[4]) {
    #pragma unroll
    for (int e = 0; e < 4; ++e) {
        int r = mt * 16 + gid4 + (e & 1) * 8;
        int c = kt * 8 + tig + (e >> 1) * 4;
        float v = Xp[r * XS + c];
        uint32_t h = to_tf32(v);
        ah[e] = h;
        al[e] = to_tf32(v - __uint_as_float(h));
    }
}
__device__ __forceinline__ void loadB(const float* W, int stride, int kt, int nt, int gid4, int tig,
                                      uint32_t &bh0, uint32_t &bh1, uint32_t &bl0, uint32_t &bl1) {
    float w0 = W[(kt * 8 + tig)     * stride + nt * 8 + gid4];
    float w1 = W[(kt * 8 + tig + 4) * stride + nt * 8 + gid4];
    bh0 = to_tf32(w0); bl0 = to_tf32(w0 - __uint_as_float(bh0));
    bh1 = to_tf32(w1); bl1 = to_tf32(w1 - __uint_as_float(bh1));
}

__global__ void __launch_bounds__(512, 1) ngp_kernel(
    const float* __restrict__ x, const float* __restrict__ dirs,
    const float* __restrict__ tables,
    const float* __restrict__ w1, const float* __restrict__ b1,
    const float* __restrict__ w2, const float* __restrict__ b2,
    const float* __restrict__ w3, const float* __restrict__ b3,
    const float* __restrict__ w4, const float* __restrict__ b4,
    const float* __restrict__ w5, const float* __restrict__ b5,
    float* __restrict__ out, int n)
{
    extern __shared__ float sw[];
    const int tid  = threadIdx.x;
    const int wid  = tid >> 5;
    const int lane = tid & 31;
    const int gid4 = lane >> 2;
    const int tig  = lane & 3;
    float* X = sw + OX + wid * 32 * XS;

    // ---- weight staging (conflict-free padded strides). Disjoint regions: no pre-sync. ----
    for (int t = tid; t < 2048; t += 512) sw[OW1 + (t >> 6) * WS + (t & 63)] = w1[t];
    for (int t = tid; t < 1024; t += 512) sw[OW2 + (t >> 4) * 24 + (t & 15)] = w2[t];
    for (int t = tid; t < 2752; t += 512) sw[OW3 + (t >> 6) * WS + (t & 63)] = w3[t];
    for (int t = tid; t < 360;  t += 512) sw[OW3 + 43 * WS + t] = 0.0f;        // W3 pad rows 43..47 (cols incl.)
    for (int t = tid; t < 4096; t += 512) sw[OW4 + (t >> 6) * WS + (t & 63)] = w4[t];
    for (int t = tid; t < 512;  t += 512) ;
    for (int t = tid; t < 512;  t += 512) sw[OW5 + t] = 0.0f;                  // W5 zero incl pad cols
    __syncthreads();                                                           // zeros before W5 fill
    for (int t = tid; t < 192;  t += 512) sw[OW5 + (t / 3) * 8 + (t % 3)] = w5[t];
    for (int t = tid; t < 64;   t += 512) { sw[OB1 + t] = b1[t]; sw[OB3 + t] = b3[t]; sw[OB4 + t] = b4[t]; }
    if (tid < 16) sw[OB2 + tid] = b2[tid];
    if (tid < 3)  sw[OB5 + tid] = b5[tid];
    __syncthreads();   // last block-wide sync; warps fully independent below

    const int gi = blockIdx.x * 512 + tid;
    const int li = (gi < n) ? gi : 0;

    // ---- position, AABB mask, normalization ----
    float px = x[li * 3 + 0] * (1.0f / 3.0f);
    float py = x[li * 3 + 1] * (1.0f / 3.0f);
    float pz = x[li * 3 + 2] * (1.0f / 3.0f);
    bool inside = (fabsf(px) < 0.5f) && (fabsf(py) < 0.5f) && (fabsf(pz) < 0.5f);
    const float HI = 1.0f - 1e-7f;
    float ux = fminf(fmaxf(px + 0.5f, 0.0f), HI);
    float uy = fminf(fmaxf(py + 0.5f, 0.0f), HI);
    float uz = fminf(fmaxf(pz + 0.5f, 0.0f), HI);
    float dx = dirs[li * 3 + 0];
    float dy = dirs[li * 3 + 1];
    float dz = dirs[li * 3 + 2];

    // ---- hash-grid encode (per point, unchanged) ----
    const int NL[16] = {16, 22, 30, 42, 58, 80, 110, 152, 210, 290, 400, 552, 762, 1052, 1452, 2004};
    const float2* __restrict__ tab2 = reinterpret_cast<const float2*>(tables);
    F2 feat[16];
    #pragma unroll
    for (int L = 0; L < 16; ++L) {
        float sx = ux * (float)NL[L], sy = uy * (float)NL[L], sz = uz * (float)NL[L];
        float fx = floorf(sx), fy = floorf(sy), fz = floorf(sz);
        float tx = sx - fx, ty = sy - fy, tz = sz - fz;
        uint32_t xi0 = (uint32_t)fx, yi0 = (uint32_t)fy, zi0 = (uint32_t)fz;
        uint32_t xi1 = xi0 + 1u;
        uint32_t hy0 = yi0 * PI2, hy1 = hy0 + PI2;
        uint32_t hz0 = zi0 * PI3, hz1 = hz0 + PI3;
        const float2* tb = tab2 + (size_t)L * TSZ;
        float2 g0 = __ldg(tb + ((xi0 ^ hy0 ^ hz0) & TMASK));
        float2 g1 = __ldg(tb + ((xi1 ^ hy0 ^ hz0) & TMASK));
        float2 g2 = __ldg(tb + ((xi0 ^ hy1 ^ hz0) & TMASK));
        float2 g3 = __ldg(tb + ((xi1 ^ hy1 ^ hz0) & TMASK));
        float2 g4 = __ldg(tb + ((xi0 ^ hy0 ^ hz1) & TMASK));
        float2 g5 = __ldg(tb + ((xi1 ^ hy0 ^ hz1) & TMASK));
        float2 g6 = __ldg(tb + ((xi0 ^ hy1 ^ hz1) & TMASK));
        float2 g7 = __ldg(tb + ((xi1 ^ hy1 ^ hz1) & TMASK));
        float wx0 = 1.0f - tx, wy0 = 1.0f - ty, wz0 = 1.0f - tz;
        float w00 = wy0 * wz0, w10 = ty * wz0, w01 = wy0 * tz, w11 = ty * tz;
        float f0 = 0.0f, f1 = 0.0f, wgt;
        wgt = wx0 * w00; f0 = fmaf(wgt, g0.x, f0); f1 = fmaf(wgt, g0.y, f1);
        wgt = tx  * w00; f0 = fmaf(wgt, g1.x, f0); f1 = fmaf(wgt, g1.y, f1);
        wgt = wx0 * w10; f0 = fmaf(wgt, g2.x, f0); f1 = fmaf(wgt, g2.y, f1);
        wgt = tx  * w10; f0 = fmaf(wgt, g3.x, f0); f1 = fmaf(wgt, g3.y, f1);
        wgt = wx0 * w01; f0 = fmaf(wgt, g4.x, f0); f1 = fmaf(wgt, g4.y, f1);
        wgt = tx  * w01; f0 = fmaf(wgt, g5.x, f0); f1 = fmaf(wgt, g5.y, f1);
        wgt = wx0 * w11; f0 = fmaf(wgt, g6.x, f0); f1 = fmaf(wgt, g6.y, f1);
        wgt = tx  * w11; f0 = fmaf(wgt, g7.x, f0); f1 = fmaf(wgt, g7.y, f1);
        feat[L].f.x = f0; feat[L].f.y = f1;
    }

    // ---- stage features: row = lane (point), cols 0..31 ----
    #pragma unroll
    for (int j = 0; j < 16; ++j)
        *reinterpret_cast<ull*>(&X[lane * XS + 2 * j]) = feat[j].u;
    __syncwarp();

    // ================= L1: [32x32] @ W1[32x64] -> relu =================
    {
        float d[2][8][4];
        #pragma unroll
        for (int nt = 0; nt < 8; ++nt) {
            float bv0 = sw[OB1 + nt * 8 + 2 * tig];
            float bv1 = sw[OB1 + nt * 8 + 2 * tig + 1];
            #pragma unroll
            for (int mt = 0; mt < 2; ++mt) { d[mt][nt][0] = bv0; d[mt][nt][1] = bv1; d[mt][nt][2] = bv0; d[mt][nt][3] = bv1; }
        }
        #pragma unroll
        for (int kt = 0; kt < 4; ++kt) {
            uint32_t ah[2][4], al[2][4];
            loadA(X, 0, kt, gid4, tig, ah[0], al[0]);
            loadA(X, 1, kt, gid4, tig, ah[1], al[1]);
            #pragma unroll
            for (int nt = 0; nt < 8; ++nt) {
                uint32_t bh0, bh1, bl0, bl1;
                loadB(sw + OW1, WS, kt, nt, gid4, tig, bh0, bh1, bl0, bl1);
                mma3(d[0][nt], ah[0], al[0], bh0, bh1, bl0, bl1);
                mma3(d[1][nt], ah[1], al[1], bh0, bh1, bl0, bl1);
            }
        }
        __syncwarp();
        #pragma unroll
        for (int nt = 0; nt < 8; ++nt) {
            int c0 = nt * 8 + 2 * tig;
            #pragma unroll
            for (int mt = 0; mt < 2; ++mt) {
                int r0 = mt * 16 + gid4;
                X[r0 * XS + c0]         = fmaxf(d[mt][nt][0], 0.0f);
                X[r0 * XS + c0 + 1]     = fmaxf(d[mt][nt][1], 0.0f);
                X[(r0+8) * XS + c0]     = fmaxf(d[mt][nt][2], 0.0f);
                X[(r0+8) * XS + c0 + 1] = fmaxf(d[mt][nt][3], 0.0f);
            }
        }
        __syncwarp();
    }

    // ================= L2: [32x64] @ W2[64x16] (no relu) =================
    float sigma_my;
    {
        float d[2][2][4];
        #pragma unroll
        for (int nt = 0; nt < 2; ++nt) {
            float bv0 = sw[OB2 + nt * 8 + 2 * tig];
            float bv1 = sw[OB2 + nt * 8 + 2 * tig + 1];
            #pragma unroll
            for (int mt = 0; mt < 2; ++mt) { d[mt][nt][0] = bv0; d[mt][nt][1] = bv1; d[mt][nt][2] = bv0; d[mt][nt][3] = bv1; }
        }
        #pragma unroll
        for (int kt = 0; kt < 8; ++kt) {
            uint32_t ah[2][4], al[2][4];
            loadA(X, 0, kt, gid4, tig, ah[0], al[0]);
            loadA(X, 1, kt, gid4, tig, ah[1], al[1]);
            #pragma unroll
            for (int nt = 0; nt < 2; ++nt) {
                uint32_t bh0, bh1, bl0, bl1;
                loadB(sw + OW2, 24, kt, nt, gid4, tig, bh0, bh1, bl0, bl1);
                mma3(d[0][nt], ah[0], al[0], bh0, bh1, bl0, bl1);
                mma3(d[1][nt], ah[1], al[1], bh0, bh1, bl0, bl1);
            }
        }
        __syncwarp();
        // H2 raw -> cols 27..42
        #pragma unroll
        for (int nt = 0; nt < 2; ++nt) {
            int c0 = 27 + nt * 8 + 2 * tig;
            #pragma unroll
            for (int mt = 0; mt < 2; ++mt) {
                int r0 = mt * 16 + gid4;
                X[r0 * XS + c0]         = d[mt][nt][0];
                X[r0 * XS + c0 + 1]     = d[mt][nt][1];
                X[(r0+8) * XS + c0]     = d[mt][nt][2];
                X[(r0+8) * XS + c0 + 1] = d[mt][nt][3];
            }
        }
        // dir encoding -> cols 0..26, zeros -> 43..47 (own row)
        {
            float* row = X + lane * XS;
            row[0] = dx; row[1] = dy; row[2] = dz;
            #pragma unroll
            for (int c = 0; c < 3; ++c) {
                float dc = (c == 0) ? dx : ((c == 1) ? dy : dz);
                #pragma unroll
                for (int fq = 0; fq < 4; ++fq) {
                    float ang = dc * (float)(1 << fq);
                    row[3 + c * 4 + fq]  = __sinf(ang);
                    row[15 + c * 4 + fq] = __cosf(ang);
                }
            }
            #pragma unroll
            for (int c = 43; c < 48; ++c) row[c] = 0.0f;
        }
        __syncwarp();
        sigma_my = X[lane * XS + 27];
    }

    // ================= L3: [32x48] @ W3[48x64] -> relu =================
    {
        float d[2][8][4];
        #pragma unroll
        for (int nt = 0; nt < 8; ++nt) {
            float bv0 = sw[OB3 + nt * 8 + 2 * tig];
            float bv1 = sw[OB3 + nt * 8 + 2 * tig + 1];
            #pragma unroll
            for (int mt = 0; mt < 2; ++mt) { d[mt][nt][0] = bv0; d[mt][nt][1] = bv1; d[mt][nt][2] = bv0; d[mt][nt][3] = bv1; }
        }
        #pragma unroll
        for (int kt = 0; kt < 6; ++kt) {
            uint32_t ah[2][4], al[2][4];
            loadA(X, 0, kt, gid4, tig, ah[0], al[0]);
            loadA(X, 1, kt, gid4, tig, ah[1], al[1]);
            #pragma unroll
            for (int nt = 0; nt < 8; ++nt) {
                uint32_t bh0, bh1, bl0, bl1;
                loadB(sw + OW3, WS, kt, nt, gid4, tig, bh0, bh1, bl0, bl1);
                mma3(d[0][nt], ah[0], al[0], bh0, bh1, bl0, bl1);
                mma3(d[1][nt], ah[1], al[1], bh0, bh1, bl0, bl1);
            }
        }
        __syncwarp();
        #pragma unroll
        for (int nt = 0; nt < 8; ++nt) {
            int c0 = nt * 8 + 2 * tig;
            #pragma unroll
            for (int mt = 0; mt < 2; ++mt) {
                int r0 = mt * 16 + gid4;
                X[r0 * XS + c0]         = fmaxf(d[mt][nt][0], 0.0f);
                X[r0 * XS + c0 + 1]     = fmaxf(d[mt][nt][1], 0.0f);
                X[(r0+8) * XS + c0]     = fmaxf(d[mt][nt][2], 0.0f);
                X[(r0+8) * XS + c0 + 1] = fmaxf(d[mt][nt][3], 0.0f);
            }
        }
        __syncwarp();
    }

    // ================= L4: [32x64] @ W4[64x64] -> relu =================
    {
        float d[2][8][4];
        #pragma unroll
        for (int nt = 0; nt < 8; ++nt) {
            float bv0 = sw[OB4 + nt * 8 + 2 * tig];
            float bv1 = sw[OB4 + nt * 8 + 2 * tig + 1];
            #pragma unroll
            for (int mt = 0; mt < 2; ++mt) { d[mt][nt][0] = bv0; d[mt][nt][1] = bv1; d[mt][nt][2] = bv0; d[mt][nt][3] = bv1; }
        }
        #pragma unroll
        for (int kt = 0; kt < 8; ++kt) {
            uint32_t ah[2][4], al[2][4];
            loadA(X, 0, kt, gid4, tig, ah[0], al[0]);
            loadA(X, 1, kt, gid4, tig, ah[1], al[1]);
            #pragma unroll
            for (int nt = 0; nt < 8; ++nt) {
                uint32_t bh0, bh1, bl0, bl1;
                loadB(sw + OW4, WS, kt, nt, gid4, tig, bh0, bh1, bl0, bl1);
                mma3(d[0][nt], ah[0], al[0], bh0, bh1, bl0, bl1);
                mma3(d[1][nt], ah[1], al[1], bh0, bh1, bl0, bl1);
            }
        }
        __syncwarp();
        #pragma unroll
        for (int nt = 0; nt < 8; ++nt) {
            int c0 = nt * 8 + 2 * tig;
            #pragma unroll
            for (int mt = 0; mt < 2; ++mt) {
                int r0 = mt * 16 + gid4;
                X[r0 * XS + c0]         = fmaxf(d[mt][nt][0], 0.0f);
                X[r0 * XS + c0 + 1]     = fmaxf(d[mt][nt][1], 0.0f);
                X[(r0+8) * XS + c0]     = fmaxf(d[mt][nt][2], 0.0f);
                X[(r0+8) * XS + c0 + 1] = fmaxf(d[mt][nt][3], 0.0f);
            }
        }
        __syncwarp();
    }

    // ================= L5: [32x64] @ W5[64x3] (MMA, N padded to 8) =================
    float vr, vg, vb;
    {
        float d[2][4];
        float bv0 = (2 * tig < 3)     ? sw[OB5 + 2 * tig]     : 0.0f;
        float bv1 = (2 * tig + 1 < 3) ? sw[OB5 + 2 * tig + 1] : 0.0f;
        d[0][0] = bv0; d[0][1] = bv1; d[0][2] = bv0; d[0][3] = bv1;
        d[1][0] = bv0; d[1][1] = bv1; d[1][2] = bv0; d[1][3] = bv1;
        #pragma unroll
        for (int kt = 0; kt < 8; ++kt) {
            uint32_t ah[2][4], al[2][4];
            loadA(X, 0, kt, gid4, tig, ah[0], al[0]);
            loadA(X, 1, kt, gid4, tig, ah[1], al[1]);
            uint32_t bh0, bh1, bl0, bl1;
            loadB(sw + OW5, 8, kt, 0, gid4, tig, bh0, bh1, bl0, bl1);
            mma3(d[0], ah[0], al[0], bh0, bh1, bl0, bl1);
            mma3(d[1], ah[1], al[1], bh0, bh1, bl0, bl1);
        }
        __syncwarp();
        // scatter D cols 0..2 into X cols 0..2, then read own row
        #pragma unroll
        for (int mt = 0; mt < 2; ++mt) {
            int r0 = mt * 16 + gid4;
            if (2 * tig < 3)     { X[r0 * XS + 2 * tig]     = d[mt][0]; X[(r0+8) * XS + 2 * tig]     = d[mt][2]; }
            if (2 * tig + 1 < 3) { X[r0 * XS + 2 * tig + 1] = d[mt][1]; X[(r0+8) * XS + 2 * tig + 1] = d[mt][3]; }
        }
        __syncwarp();
        vr = X[lane * XS + 0];
        vg = X[lane * XS + 1];
        vb = X[lane * XS + 2];
    }

    // ---- outputs: [N,3] color then [N] log_sigma ----
    if (gi < n) {
        float cr = inside ? 1.0f / (1.0f + __expf(-vr)) : 0.0f;
        float cg = inside ? 1.0f / (1.0f + __expf(-vg)) : 0.0f;
        float cb = inside ? 1.0f / (1.0f + __expf(-vb)) : 0.0f;
        out[gi * 3 + 0] = cr;
        out[gi * 3 + 1] = cg;
        out[gi * 3 + 2] = cb;
        out[(size_t)3 * n + gi] = inside ? sigma_my : -100000.0f;
    }
}

extern "C" void kernel_launch(void* const* d_in, const int* in_sizes, int n_in,
                              void* d_out, int out_size) {
    const float* x      = (const float*)d_in[0];
    const float* d      = (const float*)d_in[1];
    const float* tables = (const float*)d_in[2];
    const float* w1 = (const float*)d_in[3];
    const float* b1 = (const float*)d_in[4];
    const float* w2 = (const float*)d_in[5];
    const float* b2 = (const float*)d_in[6];
    const float* w3 = (const float*)d_in[7];
    const float* b3 = (const float*)d_in[8];
    const float* w4 = (const float*)d_in[9];
    const float* b4 = (const float*)d_in[10];
    const float* w5 = (const float*)d_in[11];
    const float* b5 = (const float*)d_in[12];
    float* out = (float*)d_out;

    cudaFuncSetAttribute(ngp_kernel, cudaFuncAttributeMaxDynamicSharedMemorySize, SMEM_BYTES);

    int n = in_sizes[0] / 3;
    int blocks = (n + 511) / 512;
    ngp_kernel<<<blocks, 512, SMEM_BYTES>>>(x, d, tables, w1, b1, w2, b2, w3, b3, w4, b4, w5, b5, out, n);
}

// round 16
// speedup vs baseline: 1.6039x; 1.4259x over previous
#include <cuda_runtime.h>
#include <stdint.h>
#include <math.h>

typedef unsigned long long ull;

#define TSZ   524288u
#define TMASK 524287u
#define PI2   2654435761u
#define PI3   805459861u

#define XSP 36     // X row stride in words: (r*36+c) mod 32 = 4r+c -> conflict-free fragment loads

// ---- dynamic shared memory WORD offsets ----
// X: 16 warps x (Xhi[32][36] + Xlo[32][36]) = 16 x 2304
#define OW1H 36864   // [16][72]
#define OW1L 38016
#define OW2H 39168   // [32][24]
#define OW2L 39936
#define OW3H 40704   // [24][72] (input rows permuted: [h16, dir27, pad5])
#define OW3L 42432
#define OW4H 44160   // [32][72]
#define OW4L 46464
#define OW5H 48768   // [32][8] (cols 3..7 zero)
#define OW5L 49024
#define OB1  49280   // 64
#define OB2  49344   // 16
#define OB3  49360   // 64
#define OB4  49424   // 64
#define OB5  49488   // 8 (3 real + zero pad)
#define SW_TOTAL 49496
#define SMEM_BYTES (SW_TOTAL * 4)   // 197984 B

union F2 { float2 f; ull u; };

// pack two floats as bf16x2: e0 -> low half (element k), e1 -> high half (k+1)
__device__ __forceinline__ uint32_t bfpack(float e0, float e1) {
    uint32_t r; asm("cvt.rn.bf16x2.f32 %0, %1, %2;" : "=r"(r) : "f"(e1), "f"(e0)); return r;
}
__device__ __forceinline__ void bfsplit(float e0, float e1, uint32_t& hi, uint32_t& lo) {
    hi = bfpack(e0, e1);
    float r0 = e0 - __uint_as_float(hi << 16);
    float r1 = e1 - __uint_as_float(hi & 0xffff0000u);
    lo = bfpack(r0, r1);
}
__device__ __forceinline__ void mmabf(float (&d)[4], const uint32_t (&a)[4], uint32_t b0, uint32_t b1) {
    asm volatile("mma.sync.aligned.m16n8k16.row.col.f32.bf16.bf16.f32 "
        "{%0,%1,%2,%3},{%4,%5,%6,%7},{%8,%9},{%0,%1,%2,%3};"
        : "+f"(d[0]), "+f"(d[1]), "+f"(d[2]), "+f"(d[3])
        : "r"(a[0]), "r"(a[1]), "r"(a[2]), "r"(a[3]), "r"(b0), "r"(b1));
}

// One MLP layer on a warp-private 32-point tile, in place in X.
// KT = K/16 tiles, NT = N/8 tiles, WSTR = weight row stride (words over kp rows).
// Per-mt in-place is safe: mt reads+writes only rows [mt*16, mt*16+16).
template<int KT, int NT, int WSTR, bool RELU>
__device__ __forceinline__ void mlp_layer(uint32_t* Xh, uint32_t* Xl,
    const uint32_t* Wh, const uint32_t* Wl, const float* bias, int gid4, int tig)
{
    #pragma unroll
    for (int mt = 0; mt < 2; ++mt) {
        float d[NT][4];
        #pragma unroll
        for (int nt = 0; nt < NT; ++nt) {
            float c0 = bias[nt * 8 + 2 * tig], c1 = bias[nt * 8 + 2 * tig + 1];
            d[nt][0] = c0; d[nt][1] = c1; d[nt][2] = c0; d[nt][3] = c1;
        }
        const int r0 = mt * 16 + gid4;
        #pragma unroll
        for (int kt = 0; kt < KT; ++kt) {
            const int c0i = kt * 8 + tig;
            uint32_t ah[4], al[4];
            ah[0] = Xh[r0 * XSP + c0i];          al[0] = Xl[r0 * XSP + c0i];
            ah[1] = Xh[(r0 + 8) * XSP + c0i];    al[1] = Xl[(r0 + 8) * XSP + c0i];
            ah[2] = Xh[r0 * XSP + c0i + 4];      al[2] = Xl[r0 * XSP + c0i + 4];
            ah[3] = Xh[(r0 + 8) * XSP + c0i + 4]; al[3] = Xl[(r0 + 8) * XSP + c0i + 4];
            const uint32_t* wr0h = Wh + (kt * 8 + tig) * WSTR;
            const uint32_t* wr1h = Wh + (kt * 8 + tig + 4) * WSTR;
            const uint32_t* wr0l = Wl + (kt * 8 + tig) * WSTR;
            const uint32_t* wr1l = Wl + (kt * 8 + tig + 4) * WSTR;
            #pragma unroll
            for (int nt = 0; nt < NT; ++nt) {
                uint32_t b0h = wr0h[nt * 8 + gid4], b1h = wr1h[nt * 8 + gid4];
                uint32_t b0l = wr0l[nt * 8 + gid4], b1l = wr1l[nt * 8 + gid4];
                mmabf(d[nt], ah, b0h, b1h);   // hi*hi
                mmabf(d[nt], al, b0h, b1h);   // lo*hi
                mmabf(d[nt], ah, b0l, b1l);   // hi*lo
            }
        }
        __syncwarp();   // all fragment reads for this mt complete (mma.sync converged)
        #pragma unroll
        for (int nt = 0; nt < NT; ++nt) {
            float e0 = d[nt][0], e1 = d[nt][1], e2 = d[nt][2], e3 = d[nt][3];
            if (RELU) { e0 = fmaxf(e0, 0.0f); e1 = fmaxf(e1, 0.0f); e2 = fmaxf(e2, 0.0f); e3 = fmaxf(e3, 0.0f); }
            uint32_t h0, l0, h1, l1;
            bfsplit(e0, e1, h0, l0);
            bfsplit(e2, e3, h1, l1);
            int cc = nt * 4 + tig;
            Xh[r0 * XSP + cc] = h0;       Xl[r0 * XSP + cc] = l0;
            Xh[(r0 + 8) * XSP + cc] = h1; Xl[(r0 + 8) * XSP + cc] = l1;
        }
        __syncwarp();
    }
}

__global__ void __launch_bounds__(512, 1) ngp_kernel(
    const float* __restrict__ x, const float* __restrict__ dirs,
    const float* __restrict__ tables,
    const float* __restrict__ w1, const float* __restrict__ b1,
    const float* __restrict__ w2, const float* __restrict__ b2,
    const float* __restrict__ w3, const float* __restrict__ b3,
    const float* __restrict__ w4, const float* __restrict__ b4,
    const float* __restrict__ w5, const float* __restrict__ b5,
    float* __restrict__ out, int n)
{
    extern __shared__ float swf[];
    uint32_t* swu = reinterpret_cast<uint32_t*>(swf);
    const int tid  = threadIdx.x;
    const int wid  = tid >> 5;
    const int lane = tid & 31;
    const int gid4 = lane >> 2;
    const int tig  = lane & 3;

    // ---- weight staging: split each pair (W[2kp][n], W[2kp+1][n]) into bf16 hi/lo words ----
    for (int t = tid; t < 1024; t += 512) {           // W1 [32][64]
        int kp = t >> 6, nn = t & 63;
        uint32_t h, l; bfsplit(w1[(2 * kp) * 64 + nn], w1[(2 * kp + 1) * 64 + nn], h, l);
        swu[OW1H + kp * 72 + nn] = h; swu[OW1L + kp * 72 + nn] = l;
    }
    for (int t = tid; t < 512; t += 512) {            // W2 [64][16]
        int kp = t >> 4, nn = t & 15;
        uint32_t h, l; bfsplit(w2[(2 * kp) * 16 + nn], w2[(2 * kp + 1) * 16 + nn], h, l);
        swu[OW2H + kp * 24 + nn] = h; swu[OW2L + kp * 24 + nn] = l;
    }
    for (int t = tid; t < 1536; t += 512) {           // W3 [43][64] -> permuted rows [h16, dir27, pad5]
        int kp = t >> 6, nn = t & 63;
        int r0 = 2 * kp, r1 = 2 * kp + 1;
        float v0 = (r0 < 16) ? w3[(27 + r0) * 64 + nn] : ((r0 < 43) ? w3[(r0 - 16) * 64 + nn] : 0.0f);
        float v1 = (r1 < 16) ? w3[(27 + r1) * 64 + nn] : ((r1 < 43) ? w3[(r1 - 16) * 64 + nn] : 0.0f);
        uint32_t h, l; bfsplit(v0, v1, h, l);
        swu[OW3H + kp * 72 + nn] = h; swu[OW3L + kp * 72 + nn] = l;
    }
    for (int t = tid; t < 2048; t += 512) {           // W4 [64][64]
        int kp = t >> 6, nn = t & 63;
        uint32_t h, l; bfsplit(w4[(2 * kp) * 64 + nn], w4[(2 * kp + 1) * 64 + nn], h, l);
        swu[OW4H + kp * 72 + nn] = h; swu[OW4L + kp * 72 + nn] = l;
    }
    for (int t = tid; t < 256; t += 512) {            // W5 [64][3] -> [32kp][8]
        int kp = t >> 3, nn = t & 7;
        float v0 = (nn < 3) ? w5[(2 * kp) * 3 + nn] : 0.0f;
        float v1 = (nn < 3) ? w5[(2 * kp + 1) * 3 + nn] : 0.0f;
        uint32_t h, l; bfsplit(v0, v1, h, l);
        swu[OW5H + kp * 8 + nn] = h; swu[OW5L + kp * 8 + nn] = l;
    }
    for (int t = tid; t < 64; t += 512) { swf[OB1 + t] = b1[t]; swf[OB3 + t] = b3[t]; swf[OB4 + t] = b4[t]; }
    if (tid < 16) swf[OB2 + tid] = b2[tid];
    if (tid < 8)  swf[OB5 + tid] = (tid < 3) ? b5[tid] : 0.0f;
    __syncthreads();   // only block-wide sync; warps independent below

    uint32_t* Xh = swu + wid * 2304;
    uint32_t* Xl = Xh + 1152;

    const int gi = blockIdx.x * 512 + tid;
    const int li = (gi < n) ? gi : 0;

    // ---- position, AABB mask, normalization ----
    float px = x[li * 3 + 0] * (1.0f / 3.0f);
    float py = x[li * 3 + 1] * (1.0f / 3.0f);
    float pz = x[li * 3 + 2] * (1.0f / 3.0f);
    bool inside = (fabsf(px) < 0.5f) && (fabsf(py) < 0.5f) && (fabsf(pz) < 0.5f);
    const float HI = 1.0f - 1e-7f;
    float ux = fminf(fmaxf(px + 0.5f, 0.0f), HI);
    float uy = fminf(fmaxf(py + 0.5f, 0.0f), HI);
    float uz = fminf(fmaxf(pz + 0.5f, 0.0f), HI);
    float dx = dirs[li * 3 + 0];
    float dy = dirs[li * 3 + 1];
    float dz = dirs[li * 3 + 2];

    // ---- hash-grid encode ----
    const int NL[16] = {16, 22, 30, 42, 58, 80, 110, 152, 210, 290, 400, 552, 762, 1052, 1452, 2004};
    const float2* __restrict__ tab2 = reinterpret_cast<const float2*>(tables);
    #pragma unroll
    for (int L = 0; L < 16; ++L) {
        float sx = ux * (float)NL[L], sy = uy * (float)NL[L], sz = uz * (float)NL[L];
        float fx = floorf(sx), fy = floorf(sy), fz = floorf(sz);
        float tx = sx - fx, ty = sy - fy, tz = sz - fz;
        uint32_t xi0 = (uint32_t)fx, yi0 = (uint32_t)fy, zi0 = (uint32_t)fz;
        uint32_t xi1 = xi0 + 1u;
        uint32_t hy0 = yi0 * PI2, hy1 = hy0 + PI2;
        uint32_t hz0 = zi0 * PI3, hz1 = hz0 + PI3;
        const float2* tb = tab2 + (size_t)L * TSZ;
        float2 g0 = __ldg(tb + ((xi0 ^ hy0 ^ hz0) & TMASK));
        float2 g1 = __ldg(tb + ((xi1 ^ hy0 ^ hz0) & TMASK));
        float2 g2 = __ldg(tb + ((xi0 ^ hy1 ^ hz0) & TMASK));
        float2 g3 = __ldg(tb + ((xi1 ^ hy1 ^ hz0) & TMASK));
        float2 g4 = __ldg(tb + ((xi0 ^ hy0 ^ hz1) & TMASK));
        float2 g5 = __ldg(tb + ((xi1 ^ hy0 ^ hz1) & TMASK));
        float2 g6 = __ldg(tb + ((xi0 ^ hy1 ^ hz1) & TMASK));
        float2 g7 = __ldg(tb + ((xi1 ^ hy1 ^ hz1) & TMASK));
        float wx0 = 1.0f - tx, wy0 = 1.0f - ty, wz0 = 1.0f - tz;
        float w00 = wy0 * wz0, w10 = ty * wz0, w01 = wy0 * tz, w11 = ty * tz;
        float f0 = 0.0f, f1 = 0.0f, wgt;
        wgt = wx0 * w00; f0 = fmaf(wgt, g0.x, f0); f1 = fmaf(wgt, g0.y, f1);
        wgt = tx  * w00; f0 = fmaf(wgt, g1.x, f0); f1 = fmaf(wgt, g1.y, f1);
        wgt = wx0 * w10; f0 = fmaf(wgt, g2.x, f0); f1 = fmaf(wgt, g2.y, f1);
        wgt = tx  * w10; f0 = fmaf(wgt, g3.x, f0); f1 = fmaf(wgt, g3.y, f1);
        wgt = wx0 * w01; f0 = fmaf(wgt, g4.x, f0); f1 = fmaf(wgt, g4.y, f1);
        wgt = tx  * w01; f0 = fmaf(wgt, g5.x, f0); f1 = fmaf(wgt, g5.y, f1);
        wgt = wx0 * w11; f0 = fmaf(wgt, g6.x, f0); f1 = fmaf(wgt, g6.y, f1);
        wgt = tx  * w11; f0 = fmaf(wgt, g7.x, f0); f1 = fmaf(wgt, g7.y, f1);
        // stage features: row=lane (point), kp=L (cols 2L, 2L+1)
        uint32_t h, l; bfsplit(f0, f1, h, l);
        Xh[lane * XSP + L] = h; Xl[lane * XSP + L] = l;
    }
    __syncwarp();

    // ---- L1: k=32, n=64, relu ----
    mlp_layer<2, 8, 72, true >(Xh, Xl, swu + OW1H, swu + OW1L, swf + OB1, gid4, tig);
    // ---- L2: k=64, n=16, no relu; h lands at kp 0..7 ----
    mlp_layer<4, 2, 24, false>(Xh, Xl, swu + OW2H, swu + OW2L, swf + OB2, gid4, tig);

    // sigma = h[0] (col 0 = low half of kp 0)
    float sigma_my = __uint_as_float(Xh[lane * XSP + 0] << 16)
                   + __uint_as_float(Xl[lane * XSP + 0] << 16);

    // direction encoding -> cols 16..42 (kp 8..23), pad 43..47 zero
    {
        float vals[32];
        vals[0] = dx; vals[1] = dy; vals[2] = dz;
        #pragma unroll
        for (int c = 0; c < 3; ++c) {
            float dc = (c == 0) ? dx : ((c == 1) ? dy : dz);
            #pragma unroll
            for (int f = 0; f < 4; ++f) {
                float ang = dc * (float)(1 << f);
                vals[3 + c * 4 + f]  = __sinf(ang);
                vals[15 + c * 4 + f] = __cosf(ang);
            }
        }
        #pragma unroll
        for (int i = 27; i < 32; ++i) vals[i] = 0.0f;
        #pragma unroll
        for (int p = 0; p < 16; ++p) {
            uint32_t h, l; bfsplit(vals[2 * p], vals[2 * p + 1], h, l);
            Xh[lane * XSP + 8 + p] = h; Xl[lane * XSP + 8 + p] = l;
        }
    }
    __syncwarp();

    // ---- L3: k=48, n=64, relu ----
    mlp_layer<3, 8, 72, true >(Xh, Xl, swu + OW3H, swu + OW3L, swf + OB3, gid4, tig);
    // ---- L4: k=64, n=64, relu ----
    mlp_layer<4, 8, 72, true >(Xh, Xl, swu + OW4H, swu + OW4L, swf + OB4, gid4, tig);
    // ---- L5: k=64, n=8 (3 real), no relu ----
    mlp_layer<4, 1, 8,  false>(Xh, Xl, swu + OW5H, swu + OW5L, swf + OB5, gid4, tig);

    uint32_t w0h = Xh[lane * XSP + 0], w0l = Xl[lane * XSP + 0];
    uint32_t w1h_ = Xh[lane * XSP + 1], w1l_ = Xl[lane * XSP + 1];
    float vr = __uint_as_float(w0h << 16)          + __uint_as_float(w0l << 16);
    float vg = __uint_as_float(w0h & 0xffff0000u)  + __uint_as_float(w0l & 0xffff0000u);
    float vb = __uint_as_float(w1h_ << 16)         + __uint_as_float(w1l_ << 16);

    // ---- outputs: [N,3] color then [N] log_sigma ----
    if (gi < n) {
        float cr = inside ? 1.0f / (1.0f + __expf(-vr)) : 0.0f;
        float cg = inside ? 1.0f / (1.0f + __expf(-vg)) : 0.0f;
        float cb = inside ? 1.0f / (1.0f + __expf(-vb)) : 0.0f;
        out[gi * 3 + 0] = cr;
        out[gi * 3 + 1] = cg;
        out[gi * 3 + 2] = cb;
        out[(size_t)3 * n + gi] = inside ? sigma_my : -100000.0f;
    }
}

extern "C" void kernel_launch(void* const* d_in, const int* in_sizes, int n_in,
                              void* d_out, int out_size) {
    const float* x      = (const float*)d_in[0];
    const float* d      = (const float*)d_in[1];
    const float* tables = (const float*)d_in[2];
    const float* w1 = (const float*)d_in[3];
    const float* b1 = (const float*)d_in[4];
    const float* w2 = (const float*)d_in[5];
    const float* b2 = (const float*)d_in[6];
    const float* w3 = (const float*)d_in[7];
    const float* b3 = (const float*)d_in[8];
    const float* w4 = (const float*)d_in[9];
    const float* b4 = (const float*)d_in[10];
    const float* w5 = (const float*)d_in[11];
    const float* b5 = (const float*)d_in[12];
    float* out = (float*)d_out;

    cudaFuncSetAttribute(ngp_kernel, cudaFuncAttributeMaxDynamicSharedMemorySize, SMEM_BYTES);

    int n = in_sizes[0] / 3;
    int blocks = (n + 511) / 512;
    ngp_kernel<<<blocks, 512, SMEM_BYTES>>>(x, d, tables, w1, b1, w2, b2, w3, b3, w4, b4, w5, b5, out, n);
}